// round 15
// baseline (speedup 1.0000x reference)
#include <cuda_runtime.h>
#include <math.h>

// Shapes (fixed): B=4, S=128, D=256, H=8, HD=32, HID=256, NS=129
#define NEGV -1000000000.0f

// ---------------- scratch (device globals) ----------------------------------
__device__ float g_t1[512 * 256];
__device__ float g_t2[512 * 256];
__device__ float g_dh[512 * 256];
__device__ float g_dt[512 * 256];
__device__ float g_vh[512 * 256];
__device__ float g_vt[512 * 256];
__device__ float g_Pa[512 * 256];
__device__ float g_Pb[512 * 256];
__device__ float g_q[516 * 256];
__device__ float g_k[516 * 256];
__device__ float g_v[516 * 256];
__device__ float g_D[4 * 128 * 128];
__device__ float g_V[4 * 128 * 128];
__device__ float g_dot[4 * 128 * 128];
__device__ float g_invDh[512];
__device__ float g_invDt[512];
__device__ float g_S1a[512], g_Qa[512], g_S1b[512], g_Qb[512], g_dotSelf[512];
__device__ float g_qs[4 * 8 * 129];
__device__ float g_ks[4 * 8 * 129];
__device__ float g_ctx[516 * 256];
__device__ float g_M[256 * 8];
__device__ float g_biasE[8];

// ---------------- helpers ----------------------------------------------------
__device__ __forceinline__ float warpSum(float v) {
#pragma unroll
    for (int o = 16; o > 0; o >>= 1) v += __shfl_xor_sync(0xffffffffu, v, o);
    return v;
}
__device__ __forceinline__ float warpMax(float v) {
#pragma unroll
    for (int o = 16; o > 0; o >>= 1) v = fmaxf(v, __shfl_xor_sync(0xffffffffu, v, o));
    return v;
}

// ---------------- 64x64x256 fp32 GEMM tile (phase A) -------------------------
__device__ __forceinline__ void gemm_tile(const float* __restrict__ A, int M,
                                          const float* __restrict__ W,
                                          const float* __restrict__ bias,
                                          float* __restrict__ C, int doRelu,
                                          int srcSkip) {
    __shared__ __align__(16) float Ast[16][64];
    __shared__ __align__(16) float Ws[16][64];
    const int tid = threadIdx.x;
    const int rowBase = blockIdx.y * 64;
    const int colBase = blockIdx.x * 64;
    if (rowBase >= M) return;
    const int tx = tid & 15, ty = tid >> 4;
    float acc[4][4] = {};
    const int aRow = tid >> 2;
    const int aK4 = (tid & 3) * 4;
    const int wK = tid >> 4;
    const int wC4 = (tid & 15) * 4;
    int row = rowBase + aRow;
    int srow = srcSkip ? (row + (row >> 7) + 1) : row;
    for (int k0 = 0; k0 < 256; k0 += 16) {
        float4 av;
        if (row < M)
            av = *(const float4*)(A + (size_t)srow * 256 + k0 + aK4);
        else
            av = make_float4(0.f, 0.f, 0.f, 0.f);
        Ast[aK4 + 0][aRow] = av.x;
        Ast[aK4 + 1][aRow] = av.y;
        Ast[aK4 + 2][aRow] = av.z;
        Ast[aK4 + 3][aRow] = av.w;
        *(float4*)&Ws[wK][wC4] =
            *(const float4*)(W + (size_t)(k0 + wK) * 256 + colBase + wC4);
        __syncthreads();
#pragma unroll
        for (int kk = 0; kk < 16; kk++) {
            float4 a = *(const float4*)&Ast[kk][ty * 4];
            float4 b = *(const float4*)&Ws[kk][tx * 4];
            acc[0][0] += a.x * b.x; acc[0][1] += a.x * b.y; acc[0][2] += a.x * b.z; acc[0][3] += a.x * b.w;
            acc[1][0] += a.y * b.x; acc[1][1] += a.y * b.y; acc[1][2] += a.y * b.z; acc[1][3] += a.y * b.w;
            acc[2][0] += a.z * b.x; acc[2][1] += a.z * b.y; acc[2][2] += a.z * b.z; acc[2][3] += a.z * b.w;
            acc[3][0] += a.w * b.x; acc[3][1] += a.w * b.y; acc[3][2] += a.w * b.z; acc[3][3] += a.w * b.w;
        }
        __syncthreads();
    }
    float4 bv = bias ? *(const float4*)(bias + colBase + tx * 4)
                     : make_float4(0.f, 0.f, 0.f, 0.f);
#pragma unroll
    for (int r = 0; r < 4; r++) {
        int orow = rowBase + ty * 4 + r;
        if (orow < M) {
            float4 o;
            o.x = acc[r][0] + bv.x; o.y = acc[r][1] + bv.y;
            o.z = acc[r][2] + bv.z; o.w = acc[r][3] + bv.w;
            if (doRelu) {
                o.x = fmaxf(o.x, 0.f); o.y = fmaxf(o.y, 0.f);
                o.z = fmaxf(o.z, 0.f); o.w = fmaxf(o.w, 0.f);
            }
            *(float4*)(C + (size_t)orow * 256 + colBase + tx * 4) = o;
        }
    }
}

// ---------------- 32x64x256 fp32 GEMM tile (phases B, C) ---------------------
__device__ __forceinline__ void gemm_tile32(const float* __restrict__ A, int M,
                                            const float* __restrict__ W,
                                            const float* __restrict__ bias,
                                            float* __restrict__ C,
                                            int rowTile, int colTile) {
    __shared__ __align__(16) float Ast[16][32];
    __shared__ __align__(16) float Ws[16][64];
    const int tid = threadIdx.x;
    const int rowBase = rowTile * 32;
    const int colBase = colTile * 64;
    const int tx = tid & 15, ty = tid >> 4;
    float acc[2][4] = {};
    const int aRow = (tid & 127) >> 2;
    const int aK4 = (tid & 3) * 4;
    const int wK = tid >> 4;
    const int wC4 = (tid & 15) * 4;
    int row = rowBase + aRow;
    for (int k0 = 0; k0 < 256; k0 += 16) {
        if (tid < 128) {
            float4 av;
            if (row < M)
                av = *(const float4*)(A + (size_t)row * 256 + k0 + aK4);
            else
                av = make_float4(0.f, 0.f, 0.f, 0.f);
            Ast[aK4 + 0][aRow] = av.x;
            Ast[aK4 + 1][aRow] = av.y;
            Ast[aK4 + 2][aRow] = av.z;
            Ast[aK4 + 3][aRow] = av.w;
        }
        *(float4*)&Ws[wK][wC4] =
            *(const float4*)(W + (size_t)(k0 + wK) * 256 + colBase + wC4);
        __syncthreads();
#pragma unroll
        for (int kk = 0; kk < 16; kk++) {
            float2 a = *(const float2*)&Ast[kk][ty * 2];
            float4 b = *(const float4*)&Ws[kk][tx * 4];
            acc[0][0] += a.x * b.x; acc[0][1] += a.x * b.y;
            acc[0][2] += a.x * b.z; acc[0][3] += a.x * b.w;
            acc[1][0] += a.y * b.x; acc[1][1] += a.y * b.y;
            acc[1][2] += a.y * b.z; acc[1][3] += a.y * b.w;
        }
        __syncthreads();
    }
    float4 bv = bias ? *(const float4*)(bias + colBase + tx * 4)
                     : make_float4(0.f, 0.f, 0.f, 0.f);
#pragma unroll
    for (int r = 0; r < 2; r++) {
        int orow = rowBase + ty * 2 + r;
        if (orow < M) {
            float4 o;
            o.x = acc[r][0] + bv.x; o.y = acc[r][1] + bv.y;
            o.z = acc[r][2] + bv.z; o.w = acc[r][3] + bv.w;
            *(float4*)(C + (size_t)orow * 256 + colBase + tx * 4) = o;
        }
    }
}

// ---------------- GEMM phase A: 9 independent GEMMs (324 blocks) -------------
__global__ __launch_bounds__(256) void phaseA_kernel(
    const float* desc, const float* nv,
    const float* th_w1, const float* th_b1,
    const float* tt_w1, const float* tt_b1,
    const float* ah_w, const float* ah_b,
    const float* at_w, const float* at_b,
    const float* eu_w1, const float* eu_b1,
    const float* q_w, const float* q_b,
    const float* k_w, const float* k_b,
    const float* v_w, const float* v_b) {
    const float *A, *W, *bias;
    float* C;
    int M = 512, relu = 0, skip = 0;
    switch (blockIdx.z) {
        case 0: A = desc; W = th_w1; bias = th_b1; C = g_t1; relu = 1; break;
        case 1: A = desc; W = tt_w1; bias = tt_b1; C = g_t2; relu = 1; break;
        case 2: A = nv;   W = ah_w;  bias = ah_b;  C = g_vh; skip = 1; break;
        case 3: A = nv;   W = at_w;  bias = at_b;  C = g_vt; skip = 1; break;
        case 4: A = desc; W = eu_w1;             bias = eu_b1;  C = g_Pa; break;
        case 5: A = desc; W = eu_w1 + 256 * 256; bias = nullptr; C = g_Pb; break;
        case 6: A = nv;   W = q_w;   bias = q_b;   C = g_q; M = 516; break;
        case 7: A = nv;   W = k_w;   bias = k_b;   C = g_k; M = 516; break;
        default: A = nv;  W = v_w;   bias = v_b;   C = g_v; M = 516; break;
    }
    gemm_tile(A, M, W, bias, C, relu, skip);
}

// ---------------- GEMM phase B: dh, dt — 32x64 tiles (128 blocks) ------------
__global__ __launch_bounds__(256) void phaseB_kernel(
    const float* th_w2, const float* th_b2,
    const float* tt_w2, const float* tt_b2) {
    if (blockIdx.z == 0)
        gemm_tile32(g_t1, 512, th_w2, th_b2, g_dh, blockIdx.y, blockIdx.x);
    else
        gemm_tile32(g_t2, 512, tt_w2, tt_b2, g_dt, blockIdx.y, blockIdx.x);
}

// ---------------- mid: combo + norms + stats + 3 products, ONE launch --------
__global__ __launch_bounds__(256) void mid_kernel(
    const float* __restrict__ ap_w,
    const float* __restrict__ eu_w2,
    const float* __restrict__ eu_b2) {
    int tid = threadIdx.x;
    int bx = blockIdx.x;
    int w = tid >> 5, lane = tid & 31;
    if (bx < 516) {
        int row = bx;
        int b = row / 129, iN = row % 129;
        float qv = g_q[(size_t)row * 256 + tid] * ap_w[lane];
        float kv = g_k[(size_t)row * 256 + tid] * ap_w[32 + lane];
        qv = warpSum(qv);
        kv = warpSum(kv);
        if (lane == 0) {
            g_qs[(size_t)(b * 8 + w) * 129 + iN] = qv;
            g_ks[(size_t)(b * 8 + w) * 129 + iN] = kv;
        }
    } else if (bx == 516) {
        int c = tid;
#pragma unroll
        for (int h = 0; h < 8; h++) {
            float s = 0.f;
#pragma unroll
            for (int t = 0; t < 32; t++)
                s += eu_w2[c * 256 + h * 32 + t] * ap_w[64 + t];
            g_M[c * 8 + h] = s;
        }
        if (tid < 8) {
            float s = 0.f;
#pragma unroll
            for (int t = 0; t < 32; t++) s += eu_b2[tid * 32 + t] * ap_w[64 + t];
            g_biasE[tid] = s;
        }
    } else if (bx < 645) {
        int row = (bx - 517) * 8 + w;
        const float* src = (row < 512) ? (g_dh + (size_t)row * 256)
                                       : (g_dt + (size_t)(row - 512) * 256);
        float ss = 0.f;
#pragma unroll
        for (int t = 0; t < 8; t++) {
            float v = src[lane + t * 32];
            ss += v * v;
        }
        ss = warpSum(ss);
        if (lane == 0) {
            float inv = rsqrtf(ss);
            if (row < 512) g_invDh[row] = inv;
            else           g_invDt[row - 512] = inv;
        }
    } else if (bx < 709) {
        int r = (bx - 645) * 8 + w;
        const float* pa = g_Pa + (size_t)r * 256;
        const float* pbp = g_Pb + (size_t)r * 256;
        float s1a = 0.f, qa = 0.f, s1b = 0.f, qb = 0.f, dts = 0.f;
#pragma unroll
        for (int t = 0; t < 8; t++) {
            int c = lane + t * 32;
            float a = pa[c], bb = pbp[c];
            s1a += a; qa += a * a;
            s1b += bb; qb += bb * bb;
            dts += a * bb;
        }
        s1a = warpSum(s1a);
        qa = warpSum(qa);
        s1b = warpSum(s1b);
        qb = warpSum(qb);
        dts = warpSum(dts);
        if (lane == 0) {
            g_S1a[r] = s1a; g_Qa[r] = qa;
            g_S1b[r] = s1b; g_Qb[r] = qb;
            g_dotSelf[r] = dts;
        }
    } else {
        int pt = bx - 709;
        int jt = pt & 3, it = (pt >> 2) & 3, bp = pt >> 4;  // 0..11
        int b = bp / 3, p = bp % 3;
        const float* X = (p == 0) ? g_dh : (p == 1) ? g_vh : g_Pa;
        const float* Y = (p == 0) ? g_dt : (p == 1) ? g_vt : g_Pb;
        float* C = (p == 0) ? g_D : (p == 1) ? g_V : g_dot;
        __shared__ __align__(16) float As[16][32];
        __shared__ __align__(16) float Bs[16][32];
        int grp = tid >> 7;
        int u = tid & 127;
        int lrow = u & 31;
        int kq = (u >> 5) * 4;
        const float* srow = grp
            ? (Y + (size_t)(b * 128 + jt * 32 + lrow) * 256)
            : (X + (size_t)(b * 128 + it * 32 + lrow) * 256);
        float (*dst)[32] = grp ? Bs : As;
        int tx = tid & 15, ty = tid >> 4;
        float a00 = 0.f, a01 = 0.f, a10 = 0.f, a11 = 0.f;
        for (int k0 = 0; k0 < 256; k0 += 16) {
            float4 v = *(const float4*)(srow + k0 + kq);
            dst[kq + 0][lrow] = v.x;
            dst[kq + 1][lrow] = v.y;
            dst[kq + 2][lrow] = v.z;
            dst[kq + 3][lrow] = v.w;
            __syncthreads();
#pragma unroll
            for (int kk = 0; kk < 16; kk++) {
                float2 a = *(const float2*)&As[kk][ty * 2];
                float2 bb = *(const float2*)&Bs[kk][tx * 2];
                a00 += a.x * bb.x; a01 += a.x * bb.y;
                a10 += a.y * bb.x; a11 += a.y * bb.y;
            }
            __syncthreads();
        }
        size_t base = ((size_t)(b * 128 + it * 32 + ty * 2)) * 128 +
                      jt * 32 + tx * 2;
        *(float2*)(C + base) = make_float2(a00, a01);
        *(float2*)(C + base + 128) = make_float2(a10, a11);
    }
}

// ---------------- mega: adj + scores (2-j batched) + softmax + ctx -----------
__global__ __launch_bounds__(256, 3) void mega_kernel(
    const float* __restrict__ eu_g, const float* __restrict__ eu_beta,
    const float* __restrict__ ap_b_p, const float* __restrict__ topo,
    const float* __restrict__ alphap, float* __restrict__ attn_out) {
    int i = blockIdx.x;  // 0..128
    int b = blockIdx.y;
    __shared__ float sM[2304];     // [c][h], stride 9 (conflict-free)
    __shared__ float sks[1032];
    __shared__ float sqs[8], sbe[8];
    __shared__ float sPa[256];
    __shared__ float sGam[256], sBt[256];
    __shared__ float sS1a[128], sQa[128], sS1b[128], sQb[128], sDot[128];
    __shared__ float sAdj[128];
    __shared__ float sSc[8][132];
    __shared__ float red[8];
    int tid = threadIdx.x, w = tid >> 5, lane = tid & 31;
    for (int t = tid; t < 2048; t += 256) sM[(t >> 3) * 9 + (t & 7)] = g_M[t];
    for (int t = tid; t < 1032; t += 256) sks[t] = g_ks[(size_t)b * 1032 + t];
    if (tid < 8) {
        sqs[tid] = g_qs[(size_t)(b * 8 + tid) * 129 + i];
        sbe[tid] = g_biasE[tid];
    }
    sGam[tid] = eu_g[tid];
    sBt[tid] = eu_beta[tid];
    if (tid < 128) {
        int rr = b * 128 + tid;
        sS1a[tid] = g_S1a[rr];
        sQa[tid] = g_Qa[rr];
        sS1b[tid] = g_S1b[rr];
        sQb[tid] = g_Qb[rr];
        sDot[tid] = (i >= 1) ? g_dot[(size_t)(b * 128 + i - 1) * 128 + tid]
                             : g_dotSelf[rr];
    }
    if (i >= 1) sPa[tid] = g_Pa[(size_t)(b * 128 + i - 1) * 256 + tid];
    __syncthreads();
    // ---- adj row (i >= 1) ----
    if (i >= 1) {
        int r = b * 128 + i - 1;
        float graw = NEGV;
        if (tid < 128) {
            float d = g_D[(size_t)r * 128 + tid] * g_invDh[r] *
                      g_invDt[b * 128 + tid];
            float a = 1.f / (1.f + expf(-(d + topo[0])));
            graw = (tid == i - 1) ? NEGV : a * g_V[(size_t)r * 128 + tid];
        }
        float m = warpMax(graw);
        if (lane == 0) red[w] = m;
        __syncthreads();
        float mx = fmaxf(fmaxf(red[0], red[1]), fmaxf(red[2], red[3]));
        float alpha = fminf(fmaxf(alphap[0], 1e-5f), 1.0f);
        float thr = mx * alpha;
        float e = (tid < 128 && graw >= thr) ? expf(graw - mx) : 0.f;
        float s = warpSum(e);
        __syncthreads();
        if (lane == 0) red[w] = s;
        __syncthreads();
        float Z = red[0] + red[1] + red[2] + red[3] +
                  red[4] + red[5] + red[6] + red[7];
        float invZ = (Z > 0.f) ? 1.f / Z : 0.f;
        if (tid < 128) sAdj[tid] = e * invZ;
        __syncthreads();
    }
    // ---- scores: 2 j per warp iteration; sM loads shared across the pair ----
    float apb = ap_b_p[0];
    float S1a_i = 0.f, Qa_i = 0.f;
    if (i >= 1) {
        S1a_i = sS1a[i - 1];
        Qa_i = sQa[i - 1];
    }
    for (int t = 0; t < 9; t++) {
        int jA = w + 16 * t;
        int jB = jA + 8;
        bool vA = (jA < 129), vB = (jB < 129);
        if (!vA && !vB) break;
        float naA = 0.f, naB = 0.f;
        if (vA) {
            if (i == 0) naA = (jA == 0) ? 0.f : 1.f;
            else        naA = (jA == 0) ? 0.f : sAdj[jA - 1];
        }
        if (vB) {
            if (i == 0) naB = (jB == 0) ? 0.f : 1.f;
            else        naB = (jB == 0) ? 0.f : sAdj[jB - 1];
        }
        bool doA = vA && (naA != 0.f);
        bool doB = vB && (naB != 0.f);
        float etermA = 0.f, etermB = 0.f;
        if (doA || doB) {
            float muA = 0.f, invA = 0.f, muB = 0.f, invB = 0.f;
            const float* pbA = g_Pb;
            const float* paA = g_Pa;
            const float* pbB = g_Pb;
            const float* paB = g_Pa;
            if (doA) {
                int jg = jA - 1;
                float S1, Qs;
                if (i >= 1) {
                    S1 = S1a_i + sS1b[jg];
                    Qs = Qa_i + sQb[jg] + 2.f * sDot[jg];
                } else {
                    S1 = sS1a[jg] + sS1b[jg];
                    Qs = sQa[jg] + sQb[jg] + 2.f * sDot[jg];
                }
                muA = S1 * (1.f / 256.f);
                float var = Qs * (1.f / 256.f) - muA * muA;
                invA = rsqrtf(var + 1e-5f);
                pbA = g_Pb + (size_t)(b * 128 + jg) * 256;
                paA = g_Pa + (size_t)(b * 128 + jg) * 256;
            }
            if (doB) {
                int jg = jB - 1;
                float S1, Qs;
                if (i >= 1) {
                    S1 = S1a_i + sS1b[jg];
                    Qs = Qa_i + sQb[jg] + 2.f * sDot[jg];
                } else {
                    S1 = sS1a[jg] + sS1b[jg];
                    Qs = sQa[jg] + sQb[jg] + 2.f * sDot[jg];
                }
                muB = S1 * (1.f / 256.f);
                float var = Qs * (1.f / 256.f) - muB * muB;
                invB = rsqrtf(var + 1e-5f);
                pbB = g_Pb + (size_t)(b * 128 + jg) * 256;
                paB = g_Pa + (size_t)(b * 128 + jg) * 256;
            }
            float accA[8] = {0.f, 0.f, 0.f, 0.f, 0.f, 0.f, 0.f, 0.f};
            float accB[8] = {0.f, 0.f, 0.f, 0.f, 0.f, 0.f, 0.f, 0.f};
#pragma unroll
            for (int u = 0; u < 8; u++) {
                int cu = lane + 32 * u;
                float gam = sGam[cu], bt = sBt[cu];
                float aPart = (i >= 1) ? sPa[cu] : 0.f;
                float rA = 0.f, rB = 0.f;
                if (doA) {
                    float vvu = (i >= 1) ? (aPart + pbA[cu]) : (paA[cu] + pbA[cu]);
                    rA = fmaxf((vvu - muA) * invA * gam + bt, 0.f);
                }
                if (doB) {
                    float vvu = (i >= 1) ? (aPart + pbB[cu]) : (paB[cu] + pbB[cu]);
                    rB = fmaxf((vvu - muB) * invB * gam + bt, 0.f);
                }
                int base = cu * 9;
#pragma unroll
                for (int h = 0; h < 8; h++) {
                    float m = sM[base + h];
                    accA[h] += rA * m;
                    accB[h] += rB * m;
                }
            }
#pragma unroll
            for (int o = 16; o > 0; o >>= 1) {
#pragma unroll
                for (int h = 0; h < 8; h++) {
                    accA[h] += __shfl_xor_sync(0xffffffffu, accA[h], o);
                    accB[h] += __shfl_xor_sync(0xffffffffu, accB[h], o);
                }
            }
            if (lane < 8) {
                etermA = accA[lane] + sbe[lane];
                etermB = accB[lane] + sbe[lane];
            }
        }
        if (lane < 8) {
            if (vA)
                sSc[lane][jA] = sqs[lane] + sks[lane * 129 + jA] + apb +
                                ((naA == 0.f) ? NEGV : etermA * naA);
            if (vB)
                sSc[lane][jB] = sqs[lane] + sks[lane * 129 + jB] + apb +
                                ((naB == 0.f) ? NEGV : etermB * naB);
        }
    }
    __syncthreads();
    // ---- softmax per head (warp w == head) ----
    {
        int h = w;
        float x0 = sSc[h][lane], x1 = sSc[h][lane + 32];
        float x2 = sSc[h][lane + 64], x3 = sSc[h][lane + 96];
        float xt = (lane == 0) ? sSc[h][128] : NEGV;
        float m = fmaxf(fmaxf(x0, x1), fmaxf(fmaxf(x2, x3), xt));
        m = warpMax(m);
        float e0 = expf(x0 - m), e1 = expf(x1 - m);
        float e2 = expf(x2 - m), e3 = expf(x3 - m);
        float et = (lane == 0) ? expf(xt - m) : 0.f;
        float s = e0 + e1 + e2 + e3 + et;
        s = warpSum(s);
        float invZ = 1.f / s;
        sSc[h][lane] = e0 * invZ;
        sSc[h][lane + 32] = e1 * invZ;
        sSc[h][lane + 64] = e2 * invZ;
        sSc[h][lane + 96] = e3 * invZ;
        if (lane == 0) sSc[h][128] = et * invZ;
        if (attn_out) {
            float* ap = attn_out + ((size_t)(b * 8 + h) * 129 + i) * 129;
            ap[lane] = e0 * invZ;
            ap[lane + 32] = e1 * invZ;
            ap[lane + 64] = e2 * invZ;
            ap[lane + 96] = e3 * invZ;
            if (lane == 0) ap[128] = et * invZ;
        }
    }
    __syncthreads();
    // ---- ctx: warp h computes channels h*32+lane ----
    {
        int h = w;
        const float* vbase = g_v + (size_t)b * 129 * 256 + h * 32 + lane;
        float acc = 0.f;
#pragma unroll 4
        for (int j = 0; j < 128; j += 4) {
            acc += sSc[h][j + 0] * vbase[(size_t)(j + 0) * 256];
            acc += sSc[h][j + 1] * vbase[(size_t)(j + 1) * 256];
            acc += sSc[h][j + 2] * vbase[(size_t)(j + 2) * 256];
            acc += sSc[h][j + 3] * vbase[(size_t)(j + 3) * 256];
        }
        acc += sSc[h][128] * vbase[(size_t)128 * 256];
        g_ctx[(size_t)(b * 129 + i) * 256 + h * 32 + lane] = acc;
    }
}

// ---------------- final out GEMM: 32x64 tiles (68 blocks) --------------------
__global__ __launch_bounds__(256) void phaseC_kernel(const float* out_w,
                                                     const float* out_b,
                                                     float* out) {
    gemm_tile32(g_ctx, 516, out_w, out_b, out, blockIdx.y, blockIdx.x);
}

// ---------------- launch -----------------------------------------------------
extern "C" void kernel_launch(void* const* d_in, const int* in_sizes, int n_in,
                              void* d_out, int out_size) {
    const float* desc   = (const float*)d_in[0];
    const float* nv     = (const float*)d_in[1];
    const float* th_w1  = (const float*)d_in[2];
    const float* th_b1  = (const float*)d_in[3];
    const float* th_w2  = (const float*)d_in[4];
    const float* th_b2  = (const float*)d_in[5];
    const float* tt_w1  = (const float*)d_in[6];
    const float* tt_b1  = (const float*)d_in[7];
    const float* tt_w2  = (const float*)d_in[8];
    const float* tt_b2  = (const float*)d_in[9];
    const float* ah_w   = (const float*)d_in[10];
    const float* ah_b   = (const float*)d_in[11];
    const float* at_w   = (const float*)d_in[12];
    const float* at_b   = (const float*)d_in[13];
    const float* q_w    = (const float*)d_in[14];
    const float* q_b    = (const float*)d_in[15];
    const float* k_w    = (const float*)d_in[16];
    const float* k_b    = (const float*)d_in[17];
    const float* v_w    = (const float*)d_in[18];
    const float* v_b    = (const float*)d_in[19];
    const float* eu_w1  = (const float*)d_in[20];
    const float* eu_b1  = (const float*)d_in[21];
    const float* eu_g   = (const float*)d_in[22];
    const float* eu_beta= (const float*)d_in[23];
    const float* eu_w2  = (const float*)d_in[24];
    const float* eu_b2  = (const float*)d_in[25];
    const float* ap_w   = (const float*)d_in[26];
    const float* ap_b   = (const float*)d_in[27];
    const float* out_w  = (const float*)d_in[28];
    const float* out_b  = (const float*)d_in[29];
    const float* topo   = (const float*)d_in[30];
    const float* alphap = (const float*)d_in[31];

    const int OUT_ELEMS = 4 * 129 * 256;          // 132096
    const int ATTN_ELEMS = 4 * 8 * 129 * 129;     // 532512
    float* out = (float*)d_out;
    float* attn_out = (out_size >= OUT_ELEMS + ATTN_ELEMS) ? (out + OUT_ELEMS)
                                                           : nullptr;

    phaseA_kernel<<<dim3(4, 9, 9), 256>>>(desc, nv, th_w1, th_b1, tt_w1, tt_b1,
                                          ah_w, ah_b, at_w, at_b, eu_w1, eu_b1,
                                          q_w, q_b, k_w, k_b, v_w, v_b);
    phaseB_kernel<<<dim3(4, 16, 2), 256>>>(th_w2, th_b2, tt_w2, tt_b2);
    mid_kernel<<<901, 256>>>(ap_w, eu_w2, eu_b2);
    mega_kernel<<<dim3(129, 4), 256>>>(eu_g, eu_beta, ap_b, topo, alphap,
                                       attn_out);
    phaseC_kernel<<<dim3(4, 17), 256>>>(out_w, out_b, out);
}

// round 16
// speedup vs baseline: 1.1969x; 1.1969x over previous
#include <cuda_runtime.h>
#include <math.h>

// Shapes (fixed): B=4, S=128, D=256, H=8, HD=32, HID=256, NS=129
#define NEGV -1000000000.0f

// ---------------- scratch (device globals) ----------------------------------
__device__ float g_t1[512 * 256];
__device__ float g_t2[512 * 256];
__device__ float g_dh[512 * 256];
__device__ float g_dt[512 * 256];
__device__ float g_vh[512 * 256];
__device__ float g_vt[512 * 256];
__device__ float g_Pa[512 * 256];
__device__ float g_Pb[512 * 256];
__device__ float g_q[516 * 256];
__device__ float g_k[516 * 256];
__device__ float g_v[516 * 256];
__device__ float g_D[4 * 128 * 128];
__device__ float g_V[4 * 128 * 128];
__device__ float g_invDh[512];
__device__ float g_invDt[512];
__device__ float g_qs[4 * 8 * 129];
__device__ float g_ks[4 * 8 * 129];
__device__ float g_ctx[516 * 256];
__device__ float g_M[256 * 8];
__device__ float g_biasE[8];

// ---------------- helpers ----------------------------------------------------
__device__ __forceinline__ float warpSum(float v) {
#pragma unroll
    for (int o = 16; o > 0; o >>= 1) v += __shfl_xor_sync(0xffffffffu, v, o);
    return v;
}
__device__ __forceinline__ float warpMax(float v) {
#pragma unroll
    for (int o = 16; o > 0; o >>= 1) v = fmaxf(v, __shfl_xor_sync(0xffffffffu, v, o));
    return v;
}

// ---------------- 64x64x256 fp32 GEMM tile (phase A) -------------------------
__device__ __forceinline__ void gemm_tile(const float* __restrict__ A, int M,
                                          const float* __restrict__ W,
                                          const float* __restrict__ bias,
                                          float* __restrict__ C, int doRelu,
                                          int srcSkip) {
    __shared__ __align__(16) float Ast[16][64];
    __shared__ __align__(16) float Ws[16][64];
    const int tid = threadIdx.x;
    const int rowBase = blockIdx.y * 64;
    const int colBase = blockIdx.x * 64;
    if (rowBase >= M) return;
    const int tx = tid & 15, ty = tid >> 4;
    float acc[4][4] = {};
    const int aRow = tid >> 2;
    const int aK4 = (tid & 3) * 4;
    const int wK = tid >> 4;
    const int wC4 = (tid & 15) * 4;
    int row = rowBase + aRow;
    int srow = srcSkip ? (row + (row >> 7) + 1) : row;
    for (int k0 = 0; k0 < 256; k0 += 16) {
        float4 av;
        if (row < M)
            av = *(const float4*)(A + (size_t)srow * 256 + k0 + aK4);
        else
            av = make_float4(0.f, 0.f, 0.f, 0.f);
        Ast[aK4 + 0][aRow] = av.x;
        Ast[aK4 + 1][aRow] = av.y;
        Ast[aK4 + 2][aRow] = av.z;
        Ast[aK4 + 3][aRow] = av.w;
        *(float4*)&Ws[wK][wC4] =
            *(const float4*)(W + (size_t)(k0 + wK) * 256 + colBase + wC4);
        __syncthreads();
#pragma unroll
        for (int kk = 0; kk < 16; kk++) {
            float4 a = *(const float4*)&Ast[kk][ty * 4];
            float4 b = *(const float4*)&Ws[kk][tx * 4];
            acc[0][0] += a.x * b.x; acc[0][1] += a.x * b.y; acc[0][2] += a.x * b.z; acc[0][3] += a.x * b.w;
            acc[1][0] += a.y * b.x; acc[1][1] += a.y * b.y; acc[1][2] += a.y * b.z; acc[1][3] += a.y * b.w;
            acc[2][0] += a.z * b.x; acc[2][1] += a.z * b.y; acc[2][2] += a.z * b.z; acc[2][3] += a.z * b.w;
            acc[3][0] += a.w * b.x; acc[3][1] += a.w * b.y; acc[3][2] += a.w * b.z; acc[3][3] += a.w * b.w;
        }
        __syncthreads();
    }
    float4 bv = bias ? *(const float4*)(bias + colBase + tx * 4)
                     : make_float4(0.f, 0.f, 0.f, 0.f);
#pragma unroll
    for (int r = 0; r < 4; r++) {
        int orow = rowBase + ty * 4 + r;
        if (orow < M) {
            float4 o;
            o.x = acc[r][0] + bv.x; o.y = acc[r][1] + bv.y;
            o.z = acc[r][2] + bv.z; o.w = acc[r][3] + bv.w;
            if (doRelu) {
                o.x = fmaxf(o.x, 0.f); o.y = fmaxf(o.y, 0.f);
                o.z = fmaxf(o.z, 0.f); o.w = fmaxf(o.w, 0.f);
            }
            *(float4*)(C + (size_t)orow * 256 + colBase + tx * 4) = o;
        }
    }
}

// ---------------- 32x64x256 fp32 GEMM tile (phases B, C) ---------------------
__device__ __forceinline__ void gemm_tile32(const float* __restrict__ A, int M,
                                            const float* __restrict__ W,
                                            const float* __restrict__ bias,
                                            float* __restrict__ C,
                                            int rowTile, int colTile) {
    __shared__ __align__(16) float Ast[16][32];
    __shared__ __align__(16) float Ws[16][64];
    const int tid = threadIdx.x;
    const int rowBase = rowTile * 32;
    const int colBase = colTile * 64;
    const int tx = tid & 15, ty = tid >> 4;
    float acc[2][4] = {};
    const int aRow = (tid & 127) >> 2;
    const int aK4 = (tid & 3) * 4;
    const int wK = tid >> 4;
    const int wC4 = (tid & 15) * 4;
    int row = rowBase + aRow;
    for (int k0 = 0; k0 < 256; k0 += 16) {
        if (tid < 128) {
            float4 av;
            if (row < M)
                av = *(const float4*)(A + (size_t)row * 256 + k0 + aK4);
            else
                av = make_float4(0.f, 0.f, 0.f, 0.f);
            Ast[aK4 + 0][aRow] = av.x;
            Ast[aK4 + 1][aRow] = av.y;
            Ast[aK4 + 2][aRow] = av.z;
            Ast[aK4 + 3][aRow] = av.w;
        }
        *(float4*)&Ws[wK][wC4] =
            *(const float4*)(W + (size_t)(k0 + wK) * 256 + colBase + wC4);
        __syncthreads();
#pragma unroll
        for (int kk = 0; kk < 16; kk++) {
            float2 a = *(const float2*)&Ast[kk][ty * 2];
            float4 b = *(const float4*)&Ws[kk][tx * 4];
            acc[0][0] += a.x * b.x; acc[0][1] += a.x * b.y;
            acc[0][2] += a.x * b.z; acc[0][3] += a.x * b.w;
            acc[1][0] += a.y * b.x; acc[1][1] += a.y * b.y;
            acc[1][2] += a.y * b.z; acc[1][3] += a.y * b.w;
        }
        __syncthreads();
    }
    float4 bv = bias ? *(const float4*)(bias + colBase + tx * 4)
                     : make_float4(0.f, 0.f, 0.f, 0.f);
#pragma unroll
    for (int r = 0; r < 2; r++) {
        int orow = rowBase + ty * 2 + r;
        if (orow < M) {
            float4 o;
            o.x = acc[r][0] + bv.x; o.y = acc[r][1] + bv.y;
            o.z = acc[r][2] + bv.z; o.w = acc[r][3] + bv.w;
            *(float4*)(C + (size_t)orow * 256 + colBase + tx * 4) = o;
        }
    }
}

// ---------------- GEMM phase A: 9 independent GEMMs (324 blocks) -------------
__global__ __launch_bounds__(256) void phaseA_kernel(
    const float* desc, const float* nv,
    const float* th_w1, const float* th_b1,
    const float* tt_w1, const float* tt_b1,
    const float* ah_w, const float* ah_b,
    const float* at_w, const float* at_b,
    const float* eu_w1, const float* eu_b1,
    const float* q_w, const float* q_b,
    const float* k_w, const float* k_b,
    const float* v_w, const float* v_b) {
    const float *A, *W, *bias;
    float* C;
    int M = 512, relu = 0, skip = 0;
    switch (blockIdx.z) {
        case 0: A = desc; W = th_w1; bias = th_b1; C = g_t1; relu = 1; break;
        case 1: A = desc; W = tt_w1; bias = tt_b1; C = g_t2; relu = 1; break;
        case 2: A = nv;   W = ah_w;  bias = ah_b;  C = g_vh; skip = 1; break;
        case 3: A = nv;   W = at_w;  bias = at_b;  C = g_vt; skip = 1; break;
        case 4: A = desc; W = eu_w1;             bias = eu_b1;  C = g_Pa; break;
        case 5: A = desc; W = eu_w1 + 256 * 256; bias = nullptr; C = g_Pb; break;
        case 6: A = nv;   W = q_w;   bias = q_b;   C = g_q; M = 516; break;
        case 7: A = nv;   W = k_w;   bias = k_b;   C = g_k; M = 516; break;
        default: A = nv;  W = v_w;   bias = v_b;   C = g_v; M = 516; break;
    }
    gemm_tile(A, M, W, bias, C, relu, skip);
}

// ---------------- GEMM phase B: dh, dt — 32x64 tiles (128 blocks) ------------
__global__ __launch_bounds__(256) void phaseB_kernel(
    const float* th_w2, const float* th_b2,
    const float* tt_w2, const float* tt_b2) {
    if (blockIdx.z == 0)
        gemm_tile32(g_t1, 512, th_w2, th_b2, g_dh, blockIdx.y, blockIdx.x);
    else
        gemm_tile32(g_t2, 512, tt_w2, tt_b2, g_dt, blockIdx.y, blockIdx.x);
}

// ---------------- mid: combo (645) + products (128) in ONE launch ------------
// Co-scheduling hides products' latency behind combo's warps.
__global__ __launch_bounds__(256) void mid_kernel(
    const float* __restrict__ ap_w,
    const float* __restrict__ eu_w2,
    const float* __restrict__ eu_b2) {
    int tid = threadIdx.x;
    int bx = blockIdx.x;
    int w = tid >> 5, lane = tid & 31;
    if (bx < 516) {
        int row = bx;
        int b = row / 129, iN = row % 129;
        float qv = g_q[(size_t)row * 256 + tid] * ap_w[lane];
        float kv = g_k[(size_t)row * 256 + tid] * ap_w[32 + lane];
        qv = warpSum(qv);
        kv = warpSum(kv);
        if (lane == 0) {
            g_qs[(size_t)(b * 8 + w) * 129 + iN] = qv;
            g_ks[(size_t)(b * 8 + w) * 129 + iN] = kv;
        }
    } else if (bx == 516) {
        int c = tid;
#pragma unroll
        for (int h = 0; h < 8; h++) {
            float s = 0.f;
#pragma unroll
            for (int t = 0; t < 32; t++)
                s += eu_w2[c * 256 + h * 32 + t] * ap_w[64 + t];
            g_M[c * 8 + h] = s;
        }
        if (tid < 8) {
            float s = 0.f;
#pragma unroll
            for (int t = 0; t < 32; t++) s += eu_b2[tid * 32 + t] * ap_w[64 + t];
            g_biasE[tid] = s;
        }
    } else if (bx < 645) {
        // dh/dt row inverse norms: rows 0..1023 (dh 0..511, dt 512..1023)
        int row = (bx - 517) * 8 + w;
        const float* src = (row < 512) ? (g_dh + (size_t)row * 256)
                                       : (g_dt + (size_t)(row - 512) * 256);
        float ss = 0.f;
#pragma unroll
        for (int t = 0; t < 8; t++) {
            float v = src[lane + t * 32];
            ss += v * v;
        }
        ss = warpSum(ss);
        if (lane == 0) {
            float inv = rsqrtf(ss);
            if (row < 512) g_invDh[row] = inv;
            else           g_invDt[row - 512] = inv;
        }
    } else {
        // products: D = dh.dt^T, V = vh.vt^T — 32x32 tile per block
        int pt = bx - 645;
        int jt = pt & 3, it = (pt >> 2) & 3, bp = pt >> 4;
        int b = bp >> 1, p = bp & 1;
        const float* X = p ? g_vh : g_dh;
        const float* Y = p ? g_vt : g_dt;
        float* C = p ? g_V : g_D;
        __shared__ __align__(16) float As[16][32];
        __shared__ __align__(16) float Bs[16][32];
        int grp = tid >> 7;
        int u = tid & 127;
        int lrow = u & 31;
        int kq = (u >> 5) * 4;
        const float* srow = grp
            ? (Y + (size_t)(b * 128 + jt * 32 + lrow) * 256)
            : (X + (size_t)(b * 128 + it * 32 + lrow) * 256);
        float (*dst)[32] = grp ? Bs : As;
        int tx = tid & 15, ty = tid >> 4;
        float a00 = 0.f, a01 = 0.f, a10 = 0.f, a11 = 0.f;
        for (int k0 = 0; k0 < 256; k0 += 16) {
            float4 v = *(const float4*)(srow + k0 + kq);
            dst[kq + 0][lrow] = v.x;
            dst[kq + 1][lrow] = v.y;
            dst[kq + 2][lrow] = v.z;
            dst[kq + 3][lrow] = v.w;
            __syncthreads();
#pragma unroll
            for (int kk = 0; kk < 16; kk++) {
                float2 a = *(const float2*)&As[kk][ty * 2];
                float2 bb = *(const float2*)&Bs[kk][tx * 2];
                a00 += a.x * bb.x; a01 += a.x * bb.y;
                a10 += a.y * bb.x; a11 += a.y * bb.y;
            }
            __syncthreads();
        }
        size_t base = ((size_t)(b * 128 + it * 32 + ty * 2)) * 128 +
                      jt * 32 + tx * 2;
        *(float2*)(C + base) = make_float2(a00, a01);
        *(float2*)(C + base + 128) = make_float2(a10, a11);
    }
}

// ---------------- mega: adj + scores + softmax + ctx per (b,i) ---------------
__global__ __launch_bounds__(256, 3) void mega_kernel(
    const float* __restrict__ eu_g, const float* __restrict__ eu_beta,
    const float* __restrict__ ap_b_p, const float* __restrict__ topo,
    const float* __restrict__ alphap, float* __restrict__ attn_out) {
    int i = blockIdx.x;  // 0..128
    int b = blockIdx.y;
    __shared__ float sM[2304];     // [c][h], stride 9 (conflict-free)
    __shared__ float sks[1032];
    __shared__ float sqs[8], sbe[8];
    __shared__ float sPa[256];
    __shared__ float sAdj[128];
    __shared__ float sSc[8][132];
    __shared__ float red[8];
    int tid = threadIdx.x, w = tid >> 5, lane = tid & 31;
    for (int t = tid; t < 2048; t += 256) sM[(t >> 3) * 9 + (t & 7)] = g_M[t];
    for (int t = tid; t < 1032; t += 256) sks[t] = g_ks[(size_t)b * 1032 + t];
    if (tid < 8) {
        sqs[tid] = g_qs[(size_t)(b * 8 + tid) * 129 + i];
        sbe[tid] = g_biasE[tid];
    }
    if (i >= 1) sPa[tid] = g_Pa[(size_t)(b * 128 + i - 1) * 256 + tid];
    __syncthreads();
    float greg[8], btreg[8];
#pragma unroll
    for (int u = 0; u < 8; u++) {
        greg[u] = eu_g[lane + 32 * u];
        btreg[u] = eu_beta[lane + 32 * u];
    }
    // ---- adj row (i >= 1): sigmoid(D_norm + tb) * V, thresholded softmax ----
    if (i >= 1) {
        int r = b * 128 + i - 1;
        float graw = NEGV;
        if (tid < 128) {
            float d = g_D[(size_t)r * 128 + tid] * g_invDh[r] *
                      g_invDt[b * 128 + tid];
            float a = 1.f / (1.f + expf(-(d + topo[0])));
            graw = (tid == i - 1) ? NEGV : a * g_V[(size_t)r * 128 + tid];
        }
        float m = warpMax(graw);
        if (lane == 0) red[w] = m;
        __syncthreads();
        float mx = fmaxf(fmaxf(red[0], red[1]), fmaxf(red[2], red[3]));
        float alpha = fminf(fmaxf(alphap[0], 1e-5f), 1.0f);
        float thr = mx * alpha;
        float e = (tid < 128 && graw >= thr) ? expf(graw - mx) : 0.f;
        float s = warpSum(e);
        __syncthreads();
        if (lane == 0) red[w] = s;
        __syncthreads();
        float Z = red[0] + red[1] + red[2] + red[3] +
                  red[4] + red[5] + red[6] + red[7];
        float invZ = (Z > 0.f) ? 1.f / Z : 0.f;
        if (tid < 128) sAdj[tid] = e * invZ;
        __syncthreads();
    }
    // ---- scores: warp-uniform j; strided channels ----
    float apb = ap_b_p[0];
    for (int j = w; j < 129; j += 8) {
        float na;
        if (i == 0) na = (j == 0) ? 0.f : 1.f;
        else        na = (j == 0) ? 0.f : sAdj[j - 1];
        float eterm = 0.f;
        if (na != 0.f) {  // warp-uniform
            int rb = b * 128 + j - 1;
            const float* pb = g_Pb + (size_t)rb * 256;
            const float* pa = g_Pa + (size_t)rb * 256;
            float vv[8];
            if (i >= 1) {
#pragma unroll
                for (int u = 0; u < 8; u++) {
                    int cu = lane + 32 * u;
                    vv[u] = sPa[cu] + pb[cu];
                }
            } else {
#pragma unroll
                for (int u = 0; u < 8; u++) {
                    int cu = lane + 32 * u;
                    vv[u] = pa[cu] + pb[cu];
                }
            }
            float s = 0.f, sq = 0.f;
#pragma unroll
            for (int u = 0; u < 8; u++) { s += vv[u]; sq += vv[u] * vv[u]; }
#pragma unroll
            for (int o = 16; o > 0; o >>= 1) {
                s += __shfl_xor_sync(0xffffffffu, s, o);
                sq += __shfl_xor_sync(0xffffffffu, sq, o);
            }
            float mu = s * (1.f / 256.f);
            float var = sq * (1.f / 256.f) - mu * mu;
            float inv = rsqrtf(var + 1e-5f);
            float acc[8] = {0.f, 0.f, 0.f, 0.f, 0.f, 0.f, 0.f, 0.f};
#pragma unroll
            for (int u = 0; u < 8; u++) {
                float r = fmaxf((vv[u] - mu) * inv * greg[u] + btreg[u], 0.f);
                int base = (lane + 32 * u) * 9;
#pragma unroll
                for (int h = 0; h < 8; h++) acc[h] += r * sM[base + h];
            }
#pragma unroll
            for (int o = 16; o > 0; o >>= 1) {
#pragma unroll
                for (int h = 0; h < 8; h++)
                    acc[h] += __shfl_xor_sync(0xffffffffu, acc[h], o);
            }
            if (lane < 8) eterm = acc[lane] + sbe[lane];
        }
        if (lane < 8) {
            sSc[lane][j] = sqs[lane] + sks[lane * 129 + j] + apb +
                           ((na == 0.f) ? NEGV : eterm * na);
        }
    }
    __syncthreads();
    // ---- softmax per head (warp w == head) ----
    {
        int h = w;
        float x0 = sSc[h][lane], x1 = sSc[h][lane + 32];
        float x2 = sSc[h][lane + 64], x3 = sSc[h][lane + 96];
        float xt = (lane == 0) ? sSc[h][128] : NEGV;
        float m = fmaxf(fmaxf(x0, x1), fmaxf(fmaxf(x2, x3), xt));
        m = warpMax(m);
        float e0 = expf(x0 - m), e1 = expf(x1 - m);
        float e2 = expf(x2 - m), e3 = expf(x3 - m);
        float et = (lane == 0) ? expf(xt - m) : 0.f;
        float s = e0 + e1 + e2 + e3 + et;
        s = warpSum(s);
        float invZ = 1.f / s;
        sSc[h][lane] = e0 * invZ;
        sSc[h][lane + 32] = e1 * invZ;
        sSc[h][lane + 64] = e2 * invZ;
        sSc[h][lane + 96] = e3 * invZ;
        if (lane == 0) sSc[h][128] = et * invZ;
        if (attn_out) {
            float* ap = attn_out + ((size_t)(b * 8 + h) * 129 + i) * 129;
            ap[lane] = e0 * invZ;
            ap[lane + 32] = e1 * invZ;
            ap[lane + 64] = e2 * invZ;
            ap[lane + 96] = e3 * invZ;
            if (lane == 0) ap[128] = et * invZ;
        }
    }
    __syncthreads();
    // ---- ctx: warp h computes channels h*32+lane ----
    {
        int h = w;
        const float* vbase = g_v + (size_t)b * 129 * 256 + h * 32 + lane;
        float acc = 0.f;
#pragma unroll 4
        for (int j = 0; j < 128; j += 4) {
            acc += sSc[h][j + 0] * vbase[(size_t)(j + 0) * 256];
            acc += sSc[h][j + 1] * vbase[(size_t)(j + 1) * 256];
            acc += sSc[h][j + 2] * vbase[(size_t)(j + 2) * 256];
            acc += sSc[h][j + 3] * vbase[(size_t)(j + 3) * 256];
        }
        acc += sSc[h][128] * vbase[(size_t)128 * 256];
        g_ctx[(size_t)(b * 129 + i) * 256 + h * 32 + lane] = acc;
    }
}

// ---------------- final out GEMM: 32x64 tiles (68 blocks) --------------------
__global__ __launch_bounds__(256) void phaseC_kernel(const float* out_w,
                                                     const float* out_b,
                                                     float* out) {
    gemm_tile32(g_ctx, 516, out_w, out_b, out, blockIdx.y, blockIdx.x);
}

// ---------------- launch -----------------------------------------------------
extern "C" void kernel_launch(void* const* d_in, const int* in_sizes, int n_in,
                              void* d_out, int out_size) {
    const float* desc   = (const float*)d_in[0];
    const float* nv     = (const float*)d_in[1];
    const float* th_w1  = (const float*)d_in[2];
    const float* th_b1  = (const float*)d_in[3];
    const float* th_w2  = (const float*)d_in[4];
    const float* th_b2  = (const float*)d_in[5];
    const float* tt_w1  = (const float*)d_in[6];
    const float* tt_b1  = (const float*)d_in[7];
    const float* tt_w2  = (const float*)d_in[8];
    const float* tt_b2  = (const float*)d_in[9];
    const float* ah_w   = (const float*)d_in[10];
    const float* ah_b   = (const float*)d_in[11];
    const float* at_w   = (const float*)d_in[12];
    const float* at_b   = (const float*)d_in[13];
    const float* q_w    = (const float*)d_in[14];
    const float* q_b    = (const float*)d_in[15];
    const float* k_w    = (const float*)d_in[16];
    const float* k_b    = (const float*)d_in[17];
    const float* v_w    = (const float*)d_in[18];
    const float* v_b    = (const float*)d_in[19];
    const float* eu_w1  = (const float*)d_in[20];
    const float* eu_b1  = (const float*)d_in[21];
    const float* eu_g   = (const float*)d_in[22];
    const float* eu_beta= (const float*)d_in[23];
    const float* eu_w2  = (const float*)d_in[24];
    const float* eu_b2  = (const float*)d_in[25];
    const float* ap_w   = (const float*)d_in[26];
    const float* ap_b   = (const float*)d_in[27];
    const float* out_w  = (const float*)d_in[28];
    const float* out_b  = (const float*)d_in[29];
    const float* topo   = (const float*)d_in[30];
    const float* alphap = (const float*)d_in[31];

    const int OUT_ELEMS = 4 * 129 * 256;          // 132096
    const int ATTN_ELEMS = 4 * 8 * 129 * 129;     // 532512
    float* out = (float*)d_out;
    float* attn_out = (out_size >= OUT_ELEMS + ATTN_ELEMS) ? (out + OUT_ELEMS)
                                                           : nullptr;

    phaseA_kernel<<<dim3(4, 9, 9), 256>>>(desc, nv, th_w1, th_b1, tt_w1, tt_b1,
                                          ah_w, ah_b, at_w, at_b, eu_w1, eu_b1,
                                          q_w, q_b, k_w, k_b, v_w, v_b);
    phaseB_kernel<<<dim3(4, 16, 2), 256>>>(th_w2, th_b2, tt_w2, tt_b2);
    mid_kernel<<<773, 256>>>(ap_w, eu_w2, eu_b2);
    mega_kernel<<<dim3(129, 4), 256>>>(eu_g, eu_beta, ap_b, topo, alphap,
                                       attn_out);
    phaseC_kernel<<<dim3(4, 17), 256>>>(out_w, out_b, out);
}

// round 17
// speedup vs baseline: 1.2089x; 1.0100x over previous
#include <cuda_runtime.h>
#include <math.h>

// Shapes (fixed): B=4, S=128, D=256, H=8, HD=32, HID=256, NS=129
#define NEGV -1000000000.0f

// ---------------- scratch (device globals) ----------------------------------
__device__ float g_t1[512 * 256];
__device__ float g_t2[512 * 256];
__device__ float g_dh[512 * 256];
__device__ float g_dt[512 * 256];
__device__ float g_vh[512 * 256];
__device__ float g_vt[512 * 256];
__device__ float g_Pa[512 * 256];
__device__ float g_Pb[512 * 256];
__device__ float g_q[516 * 256];
__device__ float g_k[516 * 256];
__device__ float g_v[516 * 256];
__device__ float g_D[4 * 128 * 128];
__device__ float g_V[4 * 128 * 128];
__device__ float g_invDh[512];
__device__ float g_invDt[512];
__device__ float g_qs[4 * 8 * 129];
__device__ float g_ks[4 * 8 * 129];
__device__ float g_ctx[516 * 256];
__device__ float g_M[256 * 8];
__device__ float g_biasE[8];

// ---------------- helpers ----------------------------------------------------
__device__ __forceinline__ float warpSum(float v) {
#pragma unroll
    for (int o = 16; o > 0; o >>= 1) v += __shfl_xor_sync(0xffffffffu, v, o);
    return v;
}
__device__ __forceinline__ float warpMax(float v) {
#pragma unroll
    for (int o = 16; o > 0; o >>= 1) v = fmaxf(v, __shfl_xor_sync(0xffffffffu, v, o));
    return v;
}

// ---- packed f32x2 FMA (Blackwell): one instr = two fp32 FMAs, rn each lane --
__device__ __forceinline__ unsigned long long dup2(float x) {
    unsigned long long r;
    asm("mov.b64 %0, {%1, %1};" : "=l"(r) : "r"(__float_as_uint(x)));
    return r;
}
__device__ __forceinline__ unsigned long long fma2(unsigned long long a,
                                                   unsigned long long b,
                                                   unsigned long long c) {
    unsigned long long d;
    asm("fma.rn.f32x2 %0, %1, %2, %3;" : "=l"(d) : "l"(a), "l"(b), "l"(c));
    return d;
}
__device__ __forceinline__ float2 unpack2(unsigned long long v) {
    unsigned lo, hi;
    asm("mov.b64 {%0, %1}, %2;" : "=r"(lo), "=r"(hi) : "l"(v));
    float2 f;
    f.x = __uint_as_float(lo);
    f.y = __uint_as_float(hi);
    return f;
}

// ---------------- 64x64x256 fp32 GEMM tile (phase A), f32x2 inner ------------
__device__ __forceinline__ void gemm_tile(const float* __restrict__ A, int M,
                                          const float* __restrict__ W,
                                          const float* __restrict__ bias,
                                          float* __restrict__ C, int doRelu,
                                          int srcSkip) {
    __shared__ __align__(16) float Ast[16][64];
    __shared__ __align__(16) float Ws[16][64];
    const int tid = threadIdx.x;
    const int rowBase = blockIdx.y * 64;
    const int colBase = blockIdx.x * 64;
    if (rowBase >= M) return;
    const int tx = tid & 15, ty = tid >> 4;
    unsigned long long accp[4][2] = {};  // (c0,c1),(c2,c3) per row r
    const int aRow = tid >> 2;
    const int aK4 = (tid & 3) * 4;
    const int wK = tid >> 4;
    const int wC4 = (tid & 15) * 4;
    int row = rowBase + aRow;
    int srow = srcSkip ? (row + (row >> 7) + 1) : row;
    for (int k0 = 0; k0 < 256; k0 += 16) {
        float4 av;
        if (row < M)
            av = *(const float4*)(A + (size_t)srow * 256 + k0 + aK4);
        else
            av = make_float4(0.f, 0.f, 0.f, 0.f);
        Ast[aK4 + 0][aRow] = av.x;
        Ast[aK4 + 1][aRow] = av.y;
        Ast[aK4 + 2][aRow] = av.z;
        Ast[aK4 + 3][aRow] = av.w;
        *(float4*)&Ws[wK][wC4] =
            *(const float4*)(W + (size_t)(k0 + wK) * 256 + colBase + wC4);
        __syncthreads();
#pragma unroll
        for (int kk = 0; kk < 16; kk++) {
            float4 a = *(const float4*)&Ast[kk][ty * 4];
            const unsigned long long* bp =
                (const unsigned long long*)&Ws[kk][tx * 4];  // 16B-aligned
            unsigned long long bxy = bp[0], bzw = bp[1];
            unsigned long long a0 = dup2(a.x), a1 = dup2(a.y);
            unsigned long long a2 = dup2(a.z), a3 = dup2(a.w);
            accp[0][0] = fma2(a0, bxy, accp[0][0]);
            accp[0][1] = fma2(a0, bzw, accp[0][1]);
            accp[1][0] = fma2(a1, bxy, accp[1][0]);
            accp[1][1] = fma2(a1, bzw, accp[1][1]);
            accp[2][0] = fma2(a2, bxy, accp[2][0]);
            accp[2][1] = fma2(a2, bzw, accp[2][1]);
            accp[3][0] = fma2(a3, bxy, accp[3][0]);
            accp[3][1] = fma2(a3, bzw, accp[3][1]);
        }
        __syncthreads();
    }
    float4 bv = bias ? *(const float4*)(bias + colBase + tx * 4)
                     : make_float4(0.f, 0.f, 0.f, 0.f);
#pragma unroll
    for (int r = 0; r < 4; r++) {
        int orow = rowBase + ty * 4 + r;
        if (orow < M) {
            float2 p0 = unpack2(accp[r][0]);
            float2 p1 = unpack2(accp[r][1]);
            float4 o;
            o.x = p0.x + bv.x; o.y = p0.y + bv.y;
            o.z = p1.x + bv.z; o.w = p1.y + bv.w;
            if (doRelu) {
                o.x = fmaxf(o.x, 0.f); o.y = fmaxf(o.y, 0.f);
                o.z = fmaxf(o.z, 0.f); o.w = fmaxf(o.w, 0.f);
            }
            *(float4*)(C + (size_t)orow * 256 + colBase + tx * 4) = o;
        }
    }
}

// ---------------- 32x64x256 fp32 GEMM tile (phases B, C), f32x2 inner --------
__device__ __forceinline__ void gemm_tile32(const float* __restrict__ A, int M,
                                            const float* __restrict__ W,
                                            const float* __restrict__ bias,
                                            float* __restrict__ C,
                                            int rowTile, int colTile) {
    __shared__ __align__(16) float Ast[16][32];
    __shared__ __align__(16) float Ws[16][64];
    const int tid = threadIdx.x;
    const int rowBase = rowTile * 32;
    const int colBase = colTile * 64;
    const int tx = tid & 15, ty = tid >> 4;
    unsigned long long accp[2][2] = {};
    const int aRow = (tid & 127) >> 2;
    const int aK4 = (tid & 3) * 4;
    const int wK = tid >> 4;
    const int wC4 = (tid & 15) * 4;
    int row = rowBase + aRow;
    for (int k0 = 0; k0 < 256; k0 += 16) {
        if (tid < 128) {
            float4 av;
            if (row < M)
                av = *(const float4*)(A + (size_t)row * 256 + k0 + aK4);
            else
                av = make_float4(0.f, 0.f, 0.f, 0.f);
            Ast[aK4 + 0][aRow] = av.x;
            Ast[aK4 + 1][aRow] = av.y;
            Ast[aK4 + 2][aRow] = av.z;
            Ast[aK4 + 3][aRow] = av.w;
        }
        *(float4*)&Ws[wK][wC4] =
            *(const float4*)(W + (size_t)(k0 + wK) * 256 + colBase + wC4);
        __syncthreads();
#pragma unroll
        for (int kk = 0; kk < 16; kk++) {
            float2 a = *(const float2*)&Ast[kk][ty * 2];
            const unsigned long long* bp =
                (const unsigned long long*)&Ws[kk][tx * 4];
            unsigned long long bxy = bp[0], bzw = bp[1];
            unsigned long long a0 = dup2(a.x), a1 = dup2(a.y);
            accp[0][0] = fma2(a0, bxy, accp[0][0]);
            accp[0][1] = fma2(a0, bzw, accp[0][1]);
            accp[1][0] = fma2(a1, bxy, accp[1][0]);
            accp[1][1] = fma2(a1, bzw, accp[1][1]);
        }
        __syncthreads();
    }
    float4 bv = bias ? *(const float4*)(bias + colBase + tx * 4)
                     : make_float4(0.f, 0.f, 0.f, 0.f);
#pragma unroll
    for (int r = 0; r < 2; r++) {
        int orow = rowBase + ty * 2 + r;
        if (orow < M) {
            float2 p0 = unpack2(accp[r][0]);
            float2 p1 = unpack2(accp[r][1]);
            float4 o;
            o.x = p0.x + bv.x; o.y = p0.y + bv.y;
            o.z = p1.x + bv.z; o.w = p1.y + bv.w;
            *(float4*)(C + (size_t)orow * 256 + colBase + tx * 4) = o;
        }
    }
}

// ---------------- GEMM phase A: 9 independent GEMMs (324 blocks) -------------
__global__ __launch_bounds__(256) void phaseA_kernel(
    const float* desc, const float* nv,
    const float* th_w1, const float* th_b1,
    const float* tt_w1, const float* tt_b1,
    const float* ah_w, const float* ah_b,
    const float* at_w, const float* at_b,
    const float* eu_w1, const float* eu_b1,
    const float* q_w, const float* q_b,
    const float* k_w, const float* k_b,
    const float* v_w, const float* v_b) {
    const float *A, *W, *bias;
    float* C;
    int M = 512, relu = 0, skip = 0;
    switch (blockIdx.z) {
        case 0: A = desc; W = th_w1; bias = th_b1; C = g_t1; relu = 1; break;
        case 1: A = desc; W = tt_w1; bias = tt_b1; C = g_t2; relu = 1; break;
        case 2: A = nv;   W = ah_w;  bias = ah_b;  C = g_vh; skip = 1; break;
        case 3: A = nv;   W = at_w;  bias = at_b;  C = g_vt; skip = 1; break;
        case 4: A = desc; W = eu_w1;             bias = eu_b1;  C = g_Pa; break;
        case 5: A = desc; W = eu_w1 + 256 * 256; bias = nullptr; C = g_Pb; break;
        case 6: A = nv;   W = q_w;   bias = q_b;   C = g_q; M = 516; break;
        case 7: A = nv;   W = k_w;   bias = k_b;   C = g_k; M = 516; break;
        default: A = nv;  W = v_w;   bias = v_b;   C = g_v; M = 516; break;
    }
    gemm_tile(A, M, W, bias, C, relu, skip);
}

// ---------------- GEMM phase B: dh, dt — 32x64 tiles (128 blocks) ------------
__global__ __launch_bounds__(256) void phaseB_kernel(
    const float* th_w2, const float* th_b2,
    const float* tt_w2, const float* tt_b2) {
    if (blockIdx.z == 0)
        gemm_tile32(g_t1, 512, th_w2, th_b2, g_dh, blockIdx.y, blockIdx.x);
    else
        gemm_tile32(g_t2, 512, tt_w2, tt_b2, g_dt, blockIdx.y, blockIdx.x);
}

// ---------------- mid: combo (645) + products (128) in ONE launch ------------
__global__ __launch_bounds__(256) void mid_kernel(
    const float* __restrict__ ap_w,
    const float* __restrict__ eu_w2,
    const float* __restrict__ eu_b2) {
    int tid = threadIdx.x;
    int bx = blockIdx.x;
    int w = tid >> 5, lane = tid & 31;
    if (bx < 516) {
        int row = bx;
        int b = row / 129, iN = row % 129;
        float qv = g_q[(size_t)row * 256 + tid] * ap_w[lane];
        float kv = g_k[(size_t)row * 256 + tid] * ap_w[32 + lane];
        qv = warpSum(qv);
        kv = warpSum(kv);
        if (lane == 0) {
            g_qs[(size_t)(b * 8 + w) * 129 + iN] = qv;
            g_ks[(size_t)(b * 8 + w) * 129 + iN] = kv;
        }
    } else if (bx == 516) {
        int c = tid;
#pragma unroll
        for (int h = 0; h < 8; h++) {
            float s = 0.f;
#pragma unroll
            for (int t = 0; t < 32; t++)
                s += eu_w2[c * 256 + h * 32 + t] * ap_w[64 + t];
            g_M[c * 8 + h] = s;
        }
        if (tid < 8) {
            float s = 0.f;
#pragma unroll
            for (int t = 0; t < 32; t++) s += eu_b2[tid * 32 + t] * ap_w[64 + t];
            g_biasE[tid] = s;
        }
    } else if (bx < 645) {
        // dh/dt row inverse norms: rows 0..1023 (dh 0..511, dt 512..1023)
        int row = (bx - 517) * 8 + w;
        const float* src = (row < 512) ? (g_dh + (size_t)row * 256)
                                       : (g_dt + (size_t)(row - 512) * 256);
        float ss = 0.f;
#pragma unroll
        for (int t = 0; t < 8; t++) {
            float v = src[lane + t * 32];
            ss += v * v;
        }
        ss = warpSum(ss);
        if (lane == 0) {
            float inv = rsqrtf(ss);
            if (row < 512) g_invDh[row] = inv;
            else           g_invDt[row - 512] = inv;
        }
    } else {
        // products: D = dh.dt^T, V = vh.vt^T — 32x32 tile per block
        int pt = bx - 645;
        int jt = pt & 3, it = (pt >> 2) & 3, bp = pt >> 4;
        int b = bp >> 1, p = bp & 1;
        const float* X = p ? g_vh : g_dh;
        const float* Y = p ? g_vt : g_dt;
        float* C = p ? g_V : g_D;
        __shared__ __align__(16) float As[16][32];
        __shared__ __align__(16) float Bs[16][32];
        int grp = tid >> 7;
        int u = tid & 127;
        int lrow = u & 31;
        int kq = (u >> 5) * 4;
        const float* srow = grp
            ? (Y + (size_t)(b * 128 + jt * 32 + lrow) * 256)
            : (X + (size_t)(b * 128 + it * 32 + lrow) * 256);
        float (*dst)[32] = grp ? Bs : As;
        int tx = tid & 15, ty = tid >> 4;
        float a00 = 0.f, a01 = 0.f, a10 = 0.f, a11 = 0.f;
        for (int k0 = 0; k0 < 256; k0 += 16) {
            float4 v = *(const float4*)(srow + k0 + kq);
            dst[kq + 0][lrow] = v.x;
            dst[kq + 1][lrow] = v.y;
            dst[kq + 2][lrow] = v.z;
            dst[kq + 3][lrow] = v.w;
            __syncthreads();
#pragma unroll
            for (int kk = 0; kk < 16; kk++) {
                float2 a = *(const float2*)&As[kk][ty * 2];
                float2 bb = *(const float2*)&Bs[kk][tx * 2];
                a00 += a.x * bb.x; a01 += a.x * bb.y;
                a10 += a.y * bb.x; a11 += a.y * bb.y;
            }
            __syncthreads();
        }
        size_t base = ((size_t)(b * 128 + it * 32 + ty * 2)) * 128 +
                      jt * 32 + tx * 2;
        *(float2*)(C + base) = make_float2(a00, a01);
        *(float2*)(C + base + 128) = make_float2(a10, a11);
    }
}

// ---------------- mega: adj + scores + softmax + ctx per (b,i) ---------------
__global__ __launch_bounds__(256, 3) void mega_kernel(
    const float* __restrict__ eu_g, const float* __restrict__ eu_beta,
    const float* __restrict__ ap_b_p, const float* __restrict__ topo,
    const float* __restrict__ alphap, float* __restrict__ attn_out) {
    int i = blockIdx.x;  // 0..128
    int b = blockIdx.y;
    __shared__ float sM[2304];     // [c][h], stride 9 (conflict-free)
    __shared__ float sks[1032];
    __shared__ float sqs[8], sbe[8];
    __shared__ float sPa[256];
    __shared__ float sAdj[128];
    __shared__ float sSc[8][132];
    __shared__ float red[8];
    int tid = threadIdx.x, w = tid >> 5, lane = tid & 31;
    for (int t = tid; t < 2048; t += 256) sM[(t >> 3) * 9 + (t & 7)] = g_M[t];
    for (int t = tid; t < 1032; t += 256) sks[t] = g_ks[(size_t)b * 1032 + t];
    if (tid < 8) {
        sqs[tid] = g_qs[(size_t)(b * 8 + tid) * 129 + i];
        sbe[tid] = g_biasE[tid];
    }
    if (i >= 1) sPa[tid] = g_Pa[(size_t)(b * 128 + i - 1) * 256 + tid];
    __syncthreads();
    float greg[8], btreg[8];
#pragma unroll
    for (int u = 0; u < 8; u++) {
        greg[u] = eu_g[lane + 32 * u];
        btreg[u] = eu_beta[lane + 32 * u];
    }
    // ---- adj row (i >= 1): sigmoid(D_norm + tb) * V, thresholded softmax ----
    if (i >= 1) {
        int r = b * 128 + i - 1;
        float graw = NEGV;
        if (tid < 128) {
            float d = g_D[(size_t)r * 128 + tid] * g_invDh[r] *
                      g_invDt[b * 128 + tid];
            float a = 1.f / (1.f + expf(-(d + topo[0])));
            graw = (tid == i - 1) ? NEGV : a * g_V[(size_t)r * 128 + tid];
        }
        float m = warpMax(graw);
        if (lane == 0) red[w] = m;
        __syncthreads();
        float mx = fmaxf(fmaxf(red[0], red[1]), fmaxf(red[2], red[3]));
        float alpha = fminf(fmaxf(alphap[0], 1e-5f), 1.0f);
        float thr = mx * alpha;
        float e = (tid < 128 && graw >= thr) ? expf(graw - mx) : 0.f;
        float s = warpSum(e);
        __syncthreads();
        if (lane == 0) red[w] = s;
        __syncthreads();
        float Z = red[0] + red[1] + red[2] + red[3] +
                  red[4] + red[5] + red[6] + red[7];
        float invZ = (Z > 0.f) ? 1.f / Z : 0.f;
        if (tid < 128) sAdj[tid] = e * invZ;
        __syncthreads();
    }
    // ---- scores: warp-uniform j; strided channels ----
    float apb = ap_b_p[0];
    for (int j = w; j < 129; j += 8) {
        float na;
        if (i == 0) na = (j == 0) ? 0.f : 1.f;
        else        na = (j == 0) ? 0.f : sAdj[j - 1];
        float eterm = 0.f;
        if (na != 0.f) {  // warp-uniform
            int rb = b * 128 + j - 1;
            const float* pb = g_Pb + (size_t)rb * 256;
            const float* pa = g_Pa + (size_t)rb * 256;
            float vv[8];
            if (i >= 1) {
#pragma unroll
                for (int u = 0; u < 8; u++) {
                    int cu = lane + 32 * u;
                    vv[u] = sPa[cu] + pb[cu];
                }
            } else {
#pragma unroll
                for (int u = 0; u < 8; u++) {
                    int cu = lane + 32 * u;
                    vv[u] = pa[cu] + pb[cu];
                }
            }
            float s = 0.f, sq = 0.f;
#pragma unroll
            for (int u = 0; u < 8; u++) { s += vv[u]; sq += vv[u] * vv[u]; }
#pragma unroll
            for (int o = 16; o > 0; o >>= 1) {
                s += __shfl_xor_sync(0xffffffffu, s, o);
                sq += __shfl_xor_sync(0xffffffffu, sq, o);
            }
            float mu = s * (1.f / 256.f);
            float var = sq * (1.f / 256.f) - mu * mu;
            float inv = rsqrtf(var + 1e-5f);
            float acc[8] = {0.f, 0.f, 0.f, 0.f, 0.f, 0.f, 0.f, 0.f};
#pragma unroll
            for (int u = 0; u < 8; u++) {
                float r = fmaxf((vv[u] - mu) * inv * greg[u] + btreg[u], 0.f);
                int base = (lane + 32 * u) * 9;
#pragma unroll
                for (int h = 0; h < 8; h++) acc[h] += r * sM[base + h];
            }
#pragma unroll
            for (int o = 16; o > 0; o >>= 1) {
#pragma unroll
                for (int h = 0; h < 8; h++)
                    acc[h] += __shfl_xor_sync(0xffffffffu, acc[h], o);
            }
            if (lane < 8) eterm = acc[lane] + sbe[lane];
        }
        if (lane < 8) {
            sSc[lane][j] = sqs[lane] + sks[lane * 129 + j] + apb +
                           ((na == 0.f) ? NEGV : eterm * na);
        }
    }
    __syncthreads();
    // ---- softmax per head (warp w == head) ----
    {
        int h = w;
        float x0 = sSc[h][lane], x1 = sSc[h][lane + 32];
        float x2 = sSc[h][lane + 64], x3 = sSc[h][lane + 96];
        float xt = (lane == 0) ? sSc[h][128] : NEGV;
        float m = fmaxf(fmaxf(x0, x1), fmaxf(fmaxf(x2, x3), xt));
        m = warpMax(m);
        float e0 = expf(x0 - m), e1 = expf(x1 - m);
        float e2 = expf(x2 - m), e3 = expf(x3 - m);
        float et = (lane == 0) ? expf(xt - m) : 0.f;
        float s = e0 + e1 + e2 + e3 + et;
        s = warpSum(s);
        float invZ = 1.f / s;
        sSc[h][lane] = e0 * invZ;
        sSc[h][lane + 32] = e1 * invZ;
        sSc[h][lane + 64] = e2 * invZ;
        sSc[h][lane + 96] = e3 * invZ;
        if (lane == 0) sSc[h][128] = et * invZ;
        if (attn_out) {
            float* ap = attn_out + ((size_t)(b * 8 + h) * 129 + i) * 129;
            ap[lane] = e0 * invZ;
            ap[lane + 32] = e1 * invZ;
            ap[lane + 64] = e2 * invZ;
            ap[lane + 96] = e3 * invZ;
            if (lane == 0) ap[128] = et * invZ;
        }
    }
    __syncthreads();
    // ---- ctx: warp h computes channels h*32+lane ----
    {
        int h = w;
        const float* vbase = g_v + (size_t)b * 129 * 256 + h * 32 + lane;
        float acc = 0.f;
#pragma unroll 4
        for (int j = 0; j < 128; j += 4) {
            acc += sSc[h][j + 0] * vbase[(size_t)(j + 0) * 256];
            acc += sSc[h][j + 1] * vbase[(size_t)(j + 1) * 256];
            acc += sSc[h][j + 2] * vbase[(size_t)(j + 2) * 256];
            acc += sSc[h][j + 3] * vbase[(size_t)(j + 3) * 256];
        }
        acc += sSc[h][128] * vbase[(size_t)128 * 256];
        g_ctx[(size_t)(b * 129 + i) * 256 + h * 32 + lane] = acc;
    }
}

// ---------------- final out GEMM: 32x64 tiles (68 blocks) --------------------
__global__ __launch_bounds__(256) void phaseC_kernel(const float* out_w,
                                                     const float* out_b,
                                                     float* out) {
    gemm_tile32(g_ctx, 516, out_w, out_b, out, blockIdx.y, blockIdx.x);
}

// ---------------- launch -----------------------------------------------------
extern "C" void kernel_launch(void* const* d_in, const int* in_sizes, int n_in,
                              void* d_out, int out_size) {
    const float* desc   = (const float*)d_in[0];
    const float* nv     = (const float*)d_in[1];
    const float* th_w1  = (const float*)d_in[2];
    const float* th_b1  = (const float*)d_in[3];
    const float* th_w2  = (const float*)d_in[4];
    const float* th_b2  = (const float*)d_in[5];
    const float* tt_w1  = (const float*)d_in[6];
    const float* tt_b1  = (const float*)d_in[7];
    const float* tt_w2  = (const float*)d_in[8];
    const float* tt_b2  = (const float*)d_in[9];
    const float* ah_w   = (const float*)d_in[10];
    const float* ah_b   = (const float*)d_in[11];
    const float* at_w   = (const float*)d_in[12];
    const float* at_b   = (const float*)d_in[13];
    const float* q_w    = (const float*)d_in[14];
    const float* q_b    = (const float*)d_in[15];
    const float* k_w    = (const float*)d_in[16];
    const float* k_b    = (const float*)d_in[17];
    const float* v_w    = (const float*)d_in[18];
    const float* v_b    = (const float*)d_in[19];
    const float* eu_w1  = (const float*)d_in[20];
    const float* eu_b1  = (const float*)d_in[21];
    const float* eu_g   = (const float*)d_in[22];
    const float* eu_beta= (const float*)d_in[23];
    const float* eu_w2  = (const float*)d_in[24];
    const float* eu_b2  = (const float*)d_in[25];
    const float* ap_w   = (const float*)d_in[26];
    const float* ap_b   = (const float*)d_in[27];
    const float* out_w  = (const float*)d_in[28];
    const float* out_b  = (const float*)d_in[29];
    const float* topo   = (const float*)d_in[30];
    const float* alphap = (const float*)d_in[31];

    const int OUT_ELEMS = 4 * 129 * 256;          // 132096
    const int ATTN_ELEMS = 4 * 8 * 129 * 129;     // 532512
    float* out = (float*)d_out;
    float* attn_out = (out_size >= OUT_ELEMS + ATTN_ELEMS) ? (out + OUT_ELEMS)
                                                           : nullptr;

    phaseA_kernel<<<dim3(4, 9, 9), 256>>>(desc, nv, th_w1, th_b1, tt_w1, tt_b1,
                                          ah_w, ah_b, at_w, at_b, eu_w1, eu_b1,
                                          q_w, q_b, k_w, k_b, v_w, v_b);
    phaseB_kernel<<<dim3(4, 16, 2), 256>>>(th_w2, th_b2, tt_w2, tt_b2);
    mid_kernel<<<773, 256>>>(ap_w, eu_w2, eu_b2);
    mega_kernel<<<dim3(129, 4), 256>>>(eu_g, eu_beta, ap_b, topo, alphap,
                                       attn_out);
    phaseC_kernel<<<dim3(4, 17), 256>>>(out_w, out_b, out);
}